// round 15
// baseline (speedup 1.0000x reference)
#include <cuda_runtime.h>
#include <cuda_fp16.h>
#include <cstdint>

#define NUM_T 64
#define DIN   4096
#define DOUT  11008
#define KS    4
#define KPER  (DIN / KS)     // 1024
#define KC    64
#define NCHUNK (KPER / KC)   // 16
#define NT    64
#define SSTRIDE 72           // +8 half pad: row stride 144B, conflict-free ldmatrix
#define STAGE_BYTES (NUM_T * SSTRIDE * 2)   // 9216 (X tile only)

// Scratch (allocation-free rule: __device__ globals)
__device__ __align__(256) __half g_xq[NUM_T * DIN];
__device__ __align__(256) float  g_part[KS * NUM_T * DOUT];   // 11.27 MB

// ---------------------------------------------------------------------------
// MXFP4 block constants from amax (integer bit-pattern construction)
// ---------------------------------------------------------------------------
__device__ __forceinline__ void mk_consts(float amax, float& c6s, float& cM,
                                          uint32_t& c2s_bits) {
    if (!(amax > 0.0f)) amax = 1.0f;
    int e  = ((__float_as_int(amax) >> 23) & 0xFF) - 127;
    int se = min(max(e - 2, -127), 127);
    c6s = __int_as_float(((se + 129) << 23) | 0x400000);   // 6 * 2^se
    cM  = __int_as_float((se + 149) << 23);                // 2^(se+22) magic
    c2s_bits = (uint32_t)((se + 128) << 23);               // bits of 2^(se+1)
}

// E2M1 qdq in the t-domain; exactly matches reference (rel_err 0.0 proven).
__device__ __forceinline__ float qdq_fast(float t, float c6s, float cM,
                                          uint32_t c2s_bits) {
    float a = fminf(fabsf(t), c6s);
    uint32_t u = __float_as_uint(a);
    uint32_t r1 = (u + 0x1FFFFFu + ((u >> 22) & 1u)) & 0xFFC00000u;
    float q2 = __fadd_rn(__fadd_rn(a, cM), -cM);
    uint32_t q = (u < c2s_bits) ? __float_as_uint(q2) : r1;
    return __uint_as_float(q | (__float_as_uint(t) & 0x80000000u));
}

// pack two exact f32 values into f16x2 (lo = x, hi = y); conversion exact
__device__ __forceinline__ uint32_t pack_h2(float x, float y) {
    uint32_t r;
    asm("cvt.rn.f16x2.f32 %0, %1, %2;" : "=r"(r) : "f"(y), "f"(x));
    return r;
}

// ---------------------------------------------------------------------------
// x quant-dequant -> f16 (one MXFP block = 8 lanes x float4)
// ---------------------------------------------------------------------------
__global__ void qdq_x_kernel(const float* __restrict__ in) {
    int gtid = blockIdx.x * blockDim.x + threadIdx.x;
    int warp = gtid >> 5;
    int lane = threadIdx.x & 31;
    long base = (long)warp * 128 + (long)lane * 4;
    if (base >= NUM_T * DIN) return;
    float4 v = *reinterpret_cast<const float4*>(in + base);
    float am = fmaxf(fmaxf(fabsf(v.x), fabsf(v.y)), fmaxf(fabsf(v.z), fabsf(v.w)));
    am = fmaxf(am, __shfl_xor_sync(0xffffffffu, am, 1));
    am = fmaxf(am, __shfl_xor_sync(0xffffffffu, am, 2));
    am = fmaxf(am, __shfl_xor_sync(0xffffffffu, am, 4));
    float c6s, cM; uint32_t c2sb;
    mk_consts(am, c6s, c2sb == 0 ? cM : cM, c2sb);   // (placeholder removed below)
    // NOTE: line above replaced by direct call — kept simple:
    mk_consts(am, c6s, cM, c2sb);
    uint2 st;
    st.x = pack_h2(qdq_fast(v.x, c6s, cM, c2sb), qdq_fast(v.y, c6s, cM, c2sb));
    st.y = pack_h2(qdq_fast(v.z, c6s, cM, c2sb), qdq_fast(v.w, c6s, cM, c2sb));
    *reinterpret_cast<uint2*>(&g_xq[base]) = st;
}

// ---------------------------------------------------------------------------
// Fused GEMM: warp = m64 x n8 stripe. W quantized straight into B fragment
// registers (no W smem). X tile double-buffered in smem (A via ldmatrix).
// ---------------------------------------------------------------------------
#define LDMATRIX_X4(r0, r1, r2, r3, addr)                                        \
    asm volatile("ldmatrix.sync.aligned.m8n8.x4.shared.b16 {%0,%1,%2,%3}, [%4];" \
                 : "=r"(r0), "=r"(r1), "=r"(r2), "=r"(r3) : "r"(addr))

#define MMA16816(c, a0, a1, a2, a3, b0, b1)                                   \
    asm volatile("mma.sync.aligned.m16n8k16.row.col.f32.f16.f16.f32 "         \
                 "{%0,%1,%2,%3}, {%4,%5,%6,%7}, {%8,%9}, {%0,%1,%2,%3};"      \
                 : "+f"(c[0]), "+f"(c[1]), "+f"(c[2]), "+f"(c[3])             \
                 : "r"(a0), "r"(a1), "r"(a2), "r"(a3), "r"(b0), "r"(b1))

__global__ __launch_bounds__(256) void fused_gemm_kernel(const float* __restrict__ W) {
    __shared__ __half Xs[2][NUM_T][SSTRIDE];

    int tid  = threadIdx.x;
    int w    = tid >> 5;
    int lane = tid & 31;
    int nbase = blockIdx.x * NT;
    int kbase = blockIdx.y * KPER;

    float acc[4][4];
    #pragma unroll
    for (int g = 0; g < 4; g++)
        #pragma unroll
        for (int j = 0; j < 4; j++) acc[g][j] = 0.0f;

    int q = lane >> 3, li = lane & 7;
    // A fragment base for m-group 0; group g adds g*16 rows
    uint32_t a_base0 = (uint32_t)__cvta_generic_to_shared(
        &Xs[0][(q & 1) * 8 + li][(q >> 1) * 8]);

    // W fragment source: row per lane, pairs at 2*(lane&3) + 8j
    int wr = nbase + w * 8 + (lane >> 2);
    int wm = (lane & 3) << 1;
    const float* wp = W + (size_t)wr * DIN + kbase + wm;
    // X staging map (R5): 2 uint4 per thread
    int xr0 = tid >> 3,         xc0 = (tid & 7) * 8;
    int xr1 = (tid + 256) >> 3, xc1 = (tid & 7) * 8;
    const __half* xp0 = &g_xq[xr0 * DIN + kbase + xc0];
    const __half* xp1 = &g_xq[xr1 * DIN + kbase + xc1];

    float2   wv[8];      // 8 k-pairs of this lane's W row, chunk being quantized
    uint32_t bfrag[4][2];// B fragments for current chunk (frag f: pairs 2f, 2f+1)
    uint4    xv[2];

    auto loadw = [&](int c) {
        #pragma unroll
        for (int j = 0; j < 8; j++)
            wv[j] = *reinterpret_cast<const float2*>(wp + c * KC + 8 * j);
    };
    // quantize wv (2 MXFP blocks: pairs 0-3 = k0-31, pairs 4-7 = k32-63)
    auto quantw = [&]() {
        #pragma unroll
        for (int blk = 0; blk < 2; blk++) {
            float2* v = wv + blk * 4;
            float am = fmaxf(fmaxf(fabsf(v[0].x), fabsf(v[0].y)),
                             fmaxf(fabsf(v[1].x), fabsf(v[1].y)));
            am = fmaxf(am, fmaxf(fmaxf(fabsf(v[2].x), fabsf(v[2].y)),
                                 fmaxf(fabsf(v[3].x), fabsf(v[3].y))));
            am = fmaxf(am, __shfl_xor_sync(0xffffffffu, am, 1));
            am = fmaxf(am, __shfl_xor_sync(0xffffffffu, am, 2));  // 4-lane quad = row's 32-block
            float c6s, cM; uint32_t c2sb;
            mk_consts(am, c6s, cM, c2sb);
            #pragma unroll
            for (int j = 0; j < 4; j++) {
                uint32_t p = pack_h2(qdq_fast(v[j].x, c6s, cM, c2sb),
                                     qdq_fast(v[j].y, c6s, cM, c2sb));
                // pair index blk*4+j -> frag f=(blk*4+j)>>1, reg (j&1)
                bfrag[blk * 2 + (j >> 1)][j & 1] = p;
            }
        }
    };
    auto stagex = [&](int s) {
        *reinterpret_cast<uint4*>(&Xs[s][xr0][xc0]) = xv[0];
        *reinterpret_cast<uint4*>(&Xs[s][xr1][xc1]) = xv[1];
    };
    auto loadx = [&](int c) {
        xv[0] = *reinterpret_cast<const uint4*>(xp0 + c * KC);
        xv[1] = *reinterpret_cast<const uint4*>(xp1 + c * KC);
    };

    // -------- prologue --------
    loadw(0);
    loadx(0);
    stagex(0);
    quantw();          // bfrag = chunk 0
    loadw(1);          // wv = chunk 1
    loadx(1);
    __syncthreads();

    // -------- main loop: one barrier per chunk --------
    #pragma unroll 1
    for (int c = 0; c < NCHUNK; c++) {
        if (c + 1 < NCHUNK)
            stagex((c + 1) & 1);
        // MMA chunk c: A from Xs[c&1] (ldmatrix, all 4 m-groups), B = bfrag
        uint32_t a_s = a_base0 + (c & 1) * STAGE_BYTES;
        #pragma unroll
        for (int ks = 0; ks < 4; ks++) {
            #pragma unroll
            for (int g = 0; g < 4; g++) {
                uint32_t a0, a1, a2, a3;
                LDMATRIX_X4(a0, a1, a2, a3,
                            a_s + g * (16 * SSTRIDE * 2) + ks * 32);
                MMA16816(acc[g], a0, a1, a2, a3, bfrag[ks][0], bfrag[ks][1]);
            }
        }
        // quantize next chunk's W into bfrag (WAR on bfrag after HMMA issue)
        if (c + 1 < NCHUNK)
            quantw();
        // prefetch chunk c+2
        if (c + 2 < NCHUNK) {
            loadw(c + 2);
            loadx(c + 2);
        }
        __syncthreads();
    }

    // epilogue: fp32 partials. Warp stripe m64 x n8 at (0, nbase + w*8).
    float* pb = g_part + (size_t)blockIdx.y * NUM_T * DOUT;
    int tg = lane >> 2, tig = lane & 3;
    int col = nbase + w * 8 + tig * 2;
    #pragma unroll
    for (int g = 0; g < 4; g++) {
        int r0 = g * 16 + tg;
        *reinterpret_cast<float2*>(&pb[(size_t)r0 * DOUT + col]) =
            make_float2(acc[g][0], acc[g][1]);
        *reinterpret_cast<float2*>(&pb[(size_t)(r0 + 8) * DOUT + col]) =
            make_float2(acc[g][2], acc[g][3]);
    }
}

// ---------------------------------------------------------------------------
// Reduce K-splits + bias qdq. 1 thread = 1 float4 of output.
// ---------------------------------------------------------------------------
__global__ void reduce_bias_kernel(const float* __restrict__ bias, float* __restrict__ out) {
    int t  = blockIdx.x * blockDim.x + threadIdx.x;
    int m  = t / (DOUT / 4);
    int o  = (t % (DOUT / 4)) * 4;

    float4 b4 = *reinterpret_cast<const float4*>(bias + o);
    float am = fmaxf(fmaxf(fabsf(b4.x), fabsf(b4.y)), fmaxf(fabsf(b4.z), fabsf(b4.w)));
    am = fmaxf(am, __shfl_xor_sync(0xffffffffu, am, 1));
    am = fmaxf(am, __shfl_xor_sync(0xffffffffu, am, 2));
    am = fmaxf(am, __shfl_xor_sync(0xffffffffu, am, 4));
    float c6s, cM; uint32_t c2sb;
    mk_consts(am, c6s, cM, c2sb);

    size_t idx = (size_t)m * DOUT + o;
    const size_t ps = (size_t)NUM_T * DOUT;
    float4 r;
    r.x = qdq_fast(b4.x, c6s, cM, c2sb);
    r.y = qdq_fast(b4.y, c6s, cM, c2sb);
    r.z = qdq_fast(b4.z, c6s, cM, c2sb);
    r.w = qdq_fast(b4.w, c6s, cM, c2sb);
    #pragma unroll
    for (int s = 0; s < KS; s++) {
        float4 p = *reinterpret_cast<const float4*>(g_part + s * ps + idx);
        r.x += p.x; r.y += p.y; r.z += p.z; r.w += p.w;
    }
    *reinterpret_cast<float4*>(out + idx) = r;
}

// ---------------------------------------------------------------------------
extern "C" void kernel_launch(void* const* d_in, const int* in_sizes, int n_in,
                              void* d_out, int out_size) {
    const float* x = nullptr;
    const float* wgt = nullptr;
    const float* bias = nullptr;
    for (int i = 0; i < n_in; i++) {
        if (in_sizes[i] == NUM_T * DIN)     x    = (const float*)d_in[i];
        else if (in_sizes[i] == DOUT * DIN) wgt  = (const float*)d_in[i];
        else if (in_sizes[i] == DOUT)       bias = (const float*)d_in[i];
    }
    float* out = (float*)d_out;

    qdq_x_kernel<<<NUM_T * DIN / 4 / 128, 128>>>(x);
    fused_gemm_kernel<<<dim3(DOUT / NT, KS), 256>>>(wgt);
    reduce_bias_kernel<<<(NUM_T * DOUT / 4) / 256, 256>>>(bias, out);
    (void)out_size;
}

// round 16
// speedup vs baseline: 1.2874x; 1.2874x over previous
#include <cuda_runtime.h>
#include <cuda_fp16.h>
#include <cstdint>

#define NUM_T 64
#define DIN   4096
#define DOUT  11008
#define KS    4
#define KPER  (DIN / KS)     // 1024
#define KC    64
#define NCHUNK (KPER / KC)   // 16
#define NT    64
#define SSTRIDE 72           // +8 half pad: row stride 144B, conflict-free ldmatrix
#define STAGE_BYTES (NUM_T * SSTRIDE * 2)   // 9216

// Scratch (allocation-free rule: __device__ globals)
__device__ __align__(256) __half g_xq[NUM_T * DIN];
__device__ __align__(256) float  g_part[KS * NUM_T * DOUT];   // 11.27 MB

// ---------------------------------------------------------------------------
// MXFP4 block constants from amax (integer bit-pattern construction)
// ---------------------------------------------------------------------------
__device__ __forceinline__ void mk_consts(float amax, float& c6s, float& cM,
                                          uint32_t& c2s_bits) {
    if (!(amax > 0.0f)) amax = 1.0f;
    int e  = ((__float_as_int(amax) >> 23) & 0xFF) - 127;
    int se = min(max(e - 2, -127), 127);
    c6s = __int_as_float(((se + 129) << 23) | 0x400000);   // 6 * 2^se
    cM  = __int_as_float((se + 149) << 23);                // 2^(se+22) magic
    c2s_bits = (uint32_t)((se + 128) << 23);               // bits of 2^(se+1)
}

// E2M1 qdq in the t-domain; exactly matches reference (rel_err 0.0 proven).
__device__ __forceinline__ float qdq_fast(float t, float c6s, float cM,
                                          uint32_t c2s_bits) {
    float a = fminf(fabsf(t), c6s);
    uint32_t u = __float_as_uint(a);
    uint32_t r1 = (u + 0x1FFFFFu + ((u >> 22) & 1u)) & 0xFFC00000u;
    float q2 = __fadd_rn(__fadd_rn(a, cM), -cM);
    uint32_t q = (u < c2s_bits) ? __float_as_uint(q2) : r1;
    return __uint_as_float(q | (__float_as_uint(t) & 0x80000000u));
}

// pack two exact f32 values into f16x2 (lo = x, hi = y); conversion exact
__device__ __forceinline__ uint32_t pack_h2(float x, float y) {
    uint32_t r;
    asm("cvt.rn.f16x2.f32 %0, %1, %2;" : "=r"(r) : "f"(y), "f"(x));
    return r;
}

// ---------------------------------------------------------------------------
// x quant-dequant -> f16 (one MXFP block = 8 lanes x float4)
// ---------------------------------------------------------------------------
__global__ void qdq_x_kernel(const float* __restrict__ in) {
    int gtid = blockIdx.x * blockDim.x + threadIdx.x;
    int warp = gtid >> 5;
    int lane = threadIdx.x & 31;
    long base = (long)warp * 128 + (long)lane * 4;
    if (base >= NUM_T * DIN) return;
    float4 v = *reinterpret_cast<const float4*>(in + base);
    float am = fmaxf(fmaxf(fabsf(v.x), fabsf(v.y)), fmaxf(fabsf(v.z), fabsf(v.w)));
    am = fmaxf(am, __shfl_xor_sync(0xffffffffu, am, 1));
    am = fmaxf(am, __shfl_xor_sync(0xffffffffu, am, 2));
    am = fmaxf(am, __shfl_xor_sync(0xffffffffu, am, 4));
    float c6s, cM; uint32_t c2sb;
    mk_consts(am, c6s, cM, c2sb);
    uint2 st;
    st.x = pack_h2(qdq_fast(v.x, c6s, cM, c2sb), qdq_fast(v.y, c6s, cM, c2sb));
    st.y = pack_h2(qdq_fast(v.z, c6s, cM, c2sb), qdq_fast(v.w, c6s, cM, c2sb));
    *reinterpret_cast<uint2*>(&g_xq[base]) = st;
}

// ---------------------------------------------------------------------------
// Fused GEMM (R5 structure), W loads quad-interleaved for sector-dense LDGs:
// thread t (quad q=t&3) owns floats {4q+16j .. 4q+16j+3}, j=0..3 of row t>>2.
// LDG #j covers bytes [64j, 64j+64) contiguous per quad -> nL=8 (was 16).
// ---------------------------------------------------------------------------
#define LDMATRIX_X4(r0, r1, r2, r3, addr)                                        \
    asm volatile("ldmatrix.sync.aligned.m8n8.x4.shared.b16 {%0,%1,%2,%3}, [%4];" \
                 : "=r"(r0), "=r"(r1), "=r"(r2), "=r"(r3) : "r"(addr))

#define MMA16816(c, a0, a1, a2, a3, b0, b1)                                   \
    asm volatile("mma.sync.aligned.m16n8k16.row.col.f32.f16.f16.f32 "         \
                 "{%0,%1,%2,%3}, {%4,%5,%6,%7}, {%8,%9}, {%0,%1,%2,%3};"      \
                 : "+f"(c[0]), "+f"(c[1]), "+f"(c[2]), "+f"(c[3])             \
                 : "r"(a0), "r"(a1), "r"(a2), "r"(a3), "r"(b0), "r"(b1))

__global__ __launch_bounds__(256) void fused_gemm_kernel(const float* __restrict__ W) {
    __shared__ __half Xs[2][NUM_T][SSTRIDE];
    __shared__ __half Ws[2][NT][SSTRIDE];

    int tid  = threadIdx.x;
    int w    = tid >> 5;
    int lane = tid & 31;
    int nbase = blockIdx.x * NT;
    int kbase = blockIdx.y * KPER;
    int mrow  = (w >> 1) * 16;
    int ncol  = (w & 1) * 32;

    float acc[4][4];
    #pragma unroll
    for (int i = 0; i < 4; i++)
        #pragma unroll
        for (int j = 0; j < 4; j++) acc[i][j] = 0.0f;

    int q = lane >> 3, li = lane & 7;
    uint32_t a_base0 = (uint32_t)__cvta_generic_to_shared(
        &Xs[0][mrow + (q & 1) * 8 + li][(q >> 1) * 8]);
    uint32_t b_base0 = (uint32_t)__cvta_generic_to_shared(
        &Ws[0][ncol + (q >> 1) * 8 + li][(q & 1) * 8]);

    // W load map: 4 threads per row; quad-interleaved float4s
    int wrow = tid >> 2;
    int wq4  = (tid & 3) << 2;           // 0,4,8,12 (floats)
    const float* wp = W + (size_t)(nbase + wrow) * DIN + kbase + wq4;
    // X load map: 2 uint4 per thread (R5)
    int xr0 = tid >> 3,         xc0 = (tid & 7) * 8;
    int xr1 = (tid + 256) >> 3, xc1 = (tid & 7) * 8;
    const __half* xp0 = &g_xq[xr0 * DIN + kbase + xc0];
    const __half* xp1 = &g_xq[xr1 * DIN + kbase + xc1];

    float4 wv[4];
    uint4  xv[2];

    auto loadw = [&](int c) {
        #pragma unroll
        for (int j = 0; j < 4; j++)
            wv[j] = *reinterpret_cast<const float4*>(wp + c * KC + 16 * j);
    };

    auto stage = [&](int s) {
        *reinterpret_cast<uint4*>(&Xs[s][xr0][xc0]) = xv[0];
        *reinterpret_cast<uint4*>(&Xs[s][xr1][xc1]) = xv[1];
        // block A = floats 0-31 (j=0,1 over quad), block B = floats 32-63
        float amA = fmaxf(fmaxf(fabsf(wv[0].x), fabsf(wv[0].y)),
                          fmaxf(fabsf(wv[0].z), fabsf(wv[0].w)));
        amA = fmaxf(amA, fmaxf(fmaxf(fabsf(wv[1].x), fabsf(wv[1].y)),
                               fmaxf(fabsf(wv[1].z), fabsf(wv[1].w))));
        float amB = fmaxf(fmaxf(fabsf(wv[2].x), fabsf(wv[2].y)),
                          fmaxf(fabsf(wv[2].z), fabsf(wv[2].w)));
        amB = fmaxf(amB, fmaxf(fmaxf(fabsf(wv[3].x), fabsf(wv[3].y)),
                               fmaxf(fabsf(wv[3].z), fabsf(wv[3].w))));
        amA = fmaxf(amA, __shfl_xor_sync(0xffffffffu, amA, 1));
        amB = fmaxf(amB, __shfl_xor_sync(0xffffffffu, amB, 1));
        amA = fmaxf(amA, __shfl_xor_sync(0xffffffffu, amA, 2));
        amB = fmaxf(amB, __shfl_xor_sync(0xffffffffu, amB, 2));
        float c6sA, cMA; uint32_t c2sA;
        float c6sB, cMB; uint32_t c2sB;
        mk_consts(amA, c6sA, cMA, c2sA);
        mk_consts(amB, c6sB, cMB, c2sB);
        __half* wr = &Ws[s][wrow][wq4];
        #pragma unroll
        for (int j = 0; j < 4; j++) {
            float c6s = (j < 2) ? c6sA : c6sB;
            float cM  = (j < 2) ? cMA  : cMB;
            uint32_t c2s = (j < 2) ? c2sA : c2sB;
            uint32_t p0 = pack_h2(qdq_fast(wv[j].x, c6s, cM, c2s),
                                  qdq_fast(wv[j].y, c6s, cM, c2s));
            uint32_t p1 = pack_h2(qdq_fast(wv[j].z, c6s, cM, c2s),
                                  qdq_fast(wv[j].w, c6s, cM, c2s));
            asm volatile("st.shared.v2.b32 [%0], {%1,%2};"
                :: "r"((uint32_t)__cvta_generic_to_shared(wr + 16 * j)),
                   "r"(p0), "r"(p1) : "memory");
        }
    };

    // -------- prologue: load chunk0, quant -> stage0, load chunk1 --------
    loadw(0);
    xv[0] = *reinterpret_cast<const uint4*>(xp0);
    xv[1] = *reinterpret_cast<const uint4*>(xp1);
    stage(0);
    loadw(1);
    xv[0] = *reinterpret_cast<const uint4*>(xp0 + KC);
    xv[1] = *reinterpret_cast<const uint4*>(xp1 + KC);
    __syncthreads();

    // -------- main loop: one barrier per chunk (R5 order) --------
    #pragma unroll 1
    for (int c16 = 0; c16 < NCHUNK; c16++) {
        if (c16 + 1 < NCHUNK)
            stage((c16 + 1) & 1);
        if (c16 + 2 < NCHUNK) {
            loadw(c16 + 2);
            int kc = (c16 + 2) * KC;
            xv[0] = *reinterpret_cast<const uint4*>(xp0 + kc);
            xv[1] = *reinterpret_cast<const uint4*>(xp1 + kc);
        }
        uint32_t a_s = a_base0 + (c16 & 1) * STAGE_BYTES;
        uint32_t b_s = b_base0 + (c16 & 1) * STAGE_BYTES;
        #pragma unroll
        for (int ks = 0; ks < 4; ks++) {
            uint32_t a0, a1, a2, a3;
            LDMATRIX_X4(a0, a1, a2, a3, a_s + ks * 32);
            #pragma unroll
            for (int nb = 0; nb < 2; nb++) {
                uint32_t b0, b1, b2, b3;
                LDMATRIX_X4(b0, b1, b2, b3, b_s + nb * 16 * SSTRIDE * 2 + ks * 32);
                MMA16816(acc[nb * 2 + 0], a0, a1, a2, a3, b0, b1);
                MMA16816(acc[nb * 2 + 1], a0, a1, a2, a3, b2, b3);
            }
        }
        __syncthreads();
    }

    // epilogue: fp32 partials (R5 layout)
    float* pb = g_part + (size_t)blockIdx.y * NUM_T * DOUT;
    int tg = lane >> 2, tig = lane & 3;
    #pragma unroll
    for (int nf = 0; nf < 4; nf++) {
        int col = nbase + ncol + nf * 8 + tig * 2;
        int r0  = mrow + tg;
        *reinterpret_cast<float2*>(&pb[(size_t)r0 * DOUT + col]) =
            make_float2(acc[nf][0], acc[nf][1]);
        *reinterpret_cast<float2*>(&pb[(size_t)(r0 + 8) * DOUT + col]) =
            make_float2(acc[nf][2], acc[nf][3]);
    }
}

// ---------------------------------------------------------------------------
// Reduce K-splits + bias qdq. 1 thread = 1 float4 of output.
// ---------------------------------------------------------------------------
__global__ void reduce_bias_kernel(const float* __restrict__ bias, float* __restrict__ out) {
    int t  = blockIdx.x * blockDim.x + threadIdx.x;
    int m  = t / (DOUT / 4);
    int o  = (t % (DOUT / 4)) * 4;

    float4 b4 = *reinterpret_cast<const float4*>(bias + o);
    float am = fmaxf(fmaxf(fabsf(b4.x), fabsf(b4.y)), fmaxf(fabsf(b4.z), fabsf(b4.w)));
    am = fmaxf(am, __shfl_xor_sync(0xffffffffu, am, 1));
    am = fmaxf(am, __shfl_xor_sync(0xffffffffu, am, 2));
    am = fmaxf(am, __shfl_xor_sync(0xffffffffu, am, 4));
    float c6s, cM; uint32_t c2sb;
    mk_consts(am, c6s, cM, c2sb);

    size_t idx = (size_t)m * DOUT + o;
    const size_t ps = (size_t)NUM_T * DOUT;
    float4 r;
    r.x = qdq_fast(b4.x, c6s, cM, c2sb);
    r.y = qdq_fast(b4.y, c6s, cM, c2sb);
    r.z = qdq_fast(b4.z, c6s, cM, c2sb);
    r.w = qdq_fast(b4.w, c6s, cM, c2sb);
    #pragma unroll
    for (int s = 0; s < KS; s++) {
        float4 p = *reinterpret_cast<const float4*>(g_part + s * ps + idx);
        r.x += p.x; r.y += p.y; r.z += p.z; r.w += p.w;
    }
    *reinterpret_cast<float4*>(out + idx) = r;
}

// ---------------------------------------------------------------------------
extern "C" void kernel_launch(void* const* d_in, const int* in_sizes, int n_in,
                              void* d_out, int out_size) {
    const float* x = nullptr;
    const float* wgt = nullptr;
    const float* bias = nullptr;
    for (int i = 0; i < n_in; i++) {
        if (in_sizes[i] == NUM_T * DIN)     x    = (const float*)d_in[i];
        else if (in_sizes[i] == DOUT * DIN) wgt  = (const float*)d_in[i];
        else if (in_sizes[i] == DOUT)       bias = (const float*)d_in[i];
    }
    float* out = (float*)d_out;

    qdq_x_kernel<<<NUM_T * DIN / 4 / 128, 128>>>(x);
    fused_gemm_kernel<<<dim3(DOUT / NT, KS), 256>>>(wgt);
    reduce_bias_kernel<<<(NUM_T * DOUT / 4) / 256, 256>>>(bias, out);
    (void)out_size;
}